// round 4
// baseline (speedup 1.0000x reference)
#include <cuda_runtime.h>
#include <cuda_fp16.h>

#define D      128
#define D4     32          // D/4 float4 per row (fp32 views)
#define DH2    32          // D/4 uint2 per row (fp16 views: 4 halves per uint2)
#define KHOPS  10

static const int NMAX = 50000;
static const int EMAX = 625000;

// ---------------- scratch (device globals; no allocation allowed) ----------
__device__ __half g_bufA[NMAX * D];     // h ping (fp16 state)
__device__ __half g_bufB[NMAX * D];     // h pong
__device__ int    g_deg[NMAX];
__device__ int    g_rowptr[NMAX + 1];
__device__ int    g_cursor[NMAX];
__device__ float  g_dinv[NMAX];
__device__ int    g_csr_src[EMAX];
__device__ float  g_csr_w[EMAX];        // dinv[src] pre-gathered
__device__ float  g_Wt[D * D];          // W transposed: Wt[k][o]
__device__ float  g_coeff[KHOPS + 1];
__device__ int    g_is64;

// ---------------- small setup kernels ---------------------------------------

// Detect whether edge_index is int64 (odd 32-bit words all zero) or int32.
__global__ void k_detect(const void* __restrict__ ei) {
    const int* a = (const int*)ei;
    int is64 = 1;
#pragma unroll
    for (int i = 1; i < 32; i += 2)
        if (a[i] != 0) is64 = 0;
    g_is64 = is64;
}

__device__ __forceinline__ int load_idx(const void* ei, long long pos) {
    if (g_is64) return (int)((const long long*)ei)[pos];
    return ((const int*)ei)[pos];
}

// coeff[k] = e^{-t} * t^k / k!
__global__ void k_coeff(const float* __restrict__ t_ptr) {
    float t = *t_ptr;
    float c = expf(-t);
    g_coeff[0] = c;
    for (int k = 1; k <= KHOPS; ++k) { c = c * t / (float)k; g_coeff[k] = c; }
}

__global__ void k_zero(int n) {
    int i = blockIdx.x * blockDim.x + threadIdx.x;
    if (i < n) g_deg[i] = 0;
}

__global__ void k_hist(const void* __restrict__ ei, int E) {
    int e = blockIdx.x * blockDim.x + threadIdx.x;
    if (e < E) {
        int dst = load_idx(ei, (long long)E + e);
        atomicAdd(&g_deg[dst], 1);
    }
}

// Single-block exclusive scan: thread-sequential chunks + shfl warp/block scan.
__global__ void __launch_bounds__(1024) k_scan(int n) {
    const int T = 1024;
    int tid  = threadIdx.x;
    int per  = (n + T - 1) / T;
    int s    = tid * per;
    int epos = s + per; if (epos > n) epos = n; if (s > n) s = n;

    int sum = 0;
    for (int i = s; i < epos; ++i) sum += g_deg[i];

    int lane = tid & 31, wid = tid >> 5;
    int v = sum;
#pragma unroll
    for (int off = 1; off < 32; off <<= 1) {
        int t = __shfl_up_sync(0xffffffffu, v, off);
        if (lane >= off) v += t;
    }
    __shared__ int wsum[32];
    if (lane == 31) wsum[wid] = v;
    __syncthreads();
    if (wid == 0) {
        int wv = wsum[lane];
#pragma unroll
        for (int off = 1; off < 32; off <<= 1) {
            int t = __shfl_up_sync(0xffffffffu, wv, off);
            if (lane >= off) wv += t;
        }
        wsum[lane] = wv;
    }
    __syncthreads();

    int excl = v - sum + (wid ? wsum[wid - 1] : 0);
    int run = excl;
    for (int i = s; i < epos; ++i) { g_rowptr[i] = run; run += g_deg[i]; }
    if (tid == T - 1) g_rowptr[n] = run;   // last thread's run == grand total
}

// cursor = rowptr copy; dinv = rsqrt(indeg + 1)  (+1 = self loop)
__global__ void k_prep(int n) {
    int i = blockIdx.x * blockDim.x + threadIdx.x;
    if (i < n) {
        g_cursor[i] = g_rowptr[i];
        g_dinv[i]   = rsqrtf((float)g_deg[i] + 1.0f);
    }
}

__global__ void k_scatter(const void* __restrict__ ei, int E) {
    int e = blockIdx.x * blockDim.x + threadIdx.x;
    if (e < E) {
        int src = load_idx(ei, e);
        int dst = load_idx(ei, (long long)E + e);
        int pos = atomicAdd(&g_cursor[dst], 1);
        g_csr_src[pos] = src;
        g_csr_w[pos]   = g_dinv[src];
    }
}

__global__ void k_transpose(const float* __restrict__ W) {
    int i = blockIdx.x * blockDim.x + threadIdx.x;
    if (i < D * D) {
        int r = i / D, c = i % D;
        g_Wt[c * D + r] = W[r * D + c];
    }
}

// ------------- fp16 pack/unpack helpers -------------------------------------
__device__ __forceinline__ void fma_h4(uint2 p, float w, float4& a) {
    float2 lo = __half22float2(*(const __half2*)&p.x);
    float2 hi = __half22float2(*(const __half2*)&p.y);
    a.x = fmaf(w, lo.x, a.x); a.y = fmaf(w, lo.y, a.y);
    a.z = fmaf(w, hi.x, a.z); a.w = fmaf(w, hi.y, a.w);
}
__device__ __forceinline__ uint2 pack_h4(float4 r) {
    __half2 lo = __floats2half2_rn(r.x, r.y);
    __half2 hi = __floats2half2_rn(r.z, r.w);
    uint2 p;
    p.x = *(const unsigned int*)&lo;
    p.y = *(const unsigned int*)&hi;
    return p;
}

// ---------------- y = x @ W^T ; h0 = fp16(y) ; out = c0*y + b ---------------
// 256 threads = 8 warps; block computes 32 rows; x tile staged in smem.
__global__ void __launch_bounds__(256) k_gemm_init(
    const float* __restrict__ x, const float* __restrict__ b,
    float* __restrict__ out, int n)
{
    __shared__ float sx[32 * D];
    int tid  = threadIdx.x;
    int warp = tid >> 5;
    int lane = tid & 31;
    int rowb = blockIdx.x * 32;
    int rows = n - rowb; if (rows > 32) rows = 32;

    // cooperative load of x tile (float4)
    const float4* x4 = (const float4*)(x + (long long)rowb * D);
    float4* sx4 = (float4*)sx;
    for (int i = tid; i < rows * D4; i += 256) sx4[i] = x4[i];
    __syncthreads();

    int r0 = warp * 4;
    if (rowb + r0 >= n) return;
    int nr = rows - r0; if (nr > 4) nr = 4; if (nr < 0) nr = 0;

    const float4* __restrict__ Wt4 = (const float4*)g_Wt;

    float4 a0 = make_float4(0.f,0.f,0.f,0.f), a1 = a0, a2 = a0, a3 = a0;

#pragma unroll 4
    for (int kc = 0; kc < D; ++kc) {
        float4 w = __ldg(&Wt4[kc * D4 + lane]);
        float v0 =             sx[(r0 + 0) * D + kc];
        float v1 = (nr > 1) ?  sx[(r0 + 1) * D + kc] : 0.f;
        float v2 = (nr > 2) ?  sx[(r0 + 2) * D + kc] : 0.f;
        float v3 = (nr > 3) ?  sx[(r0 + 3) * D + kc] : 0.f;
        a0.x = fmaf(v0, w.x, a0.x); a0.y = fmaf(v0, w.y, a0.y);
        a0.z = fmaf(v0, w.z, a0.z); a0.w = fmaf(v0, w.w, a0.w);
        a1.x = fmaf(v1, w.x, a1.x); a1.y = fmaf(v1, w.y, a1.y);
        a1.z = fmaf(v1, w.z, a1.z); a1.w = fmaf(v1, w.w, a1.w);
        a2.x = fmaf(v2, w.x, a2.x); a2.y = fmaf(v2, w.y, a2.y);
        a2.z = fmaf(v2, w.z, a2.z); a2.w = fmaf(v2, w.w, a2.w);
        a3.x = fmaf(v3, w.x, a3.x); a3.y = fmaf(v3, w.y, a3.y);
        a3.z = fmaf(v3, w.z, a3.z); a3.w = fmaf(v3, w.w, a3.w);
    }

    float c0 = g_coeff[0];
    float4 b4 = __ldg(&((const float4*)b)[lane]);
    uint2*  h0 = (uint2*)g_bufA;
    float4* o4 = (float4*)out;

    float4 accs[4] = {a0, a1, a2, a3};
#pragma unroll
    for (int j = 0; j < 4; ++j) {
        if (j < nr) {
            int idx = (rowb + r0 + j) * D4 + lane;
            float4 r = accs[j];
            h0[idx] = pack_h4(r);
            float4 o;
            o.x = fmaf(c0, r.x, b4.x);
            o.y = fmaf(c0, r.y, b4.y);
            o.z = fmaf(c0, r.z, b4.z);
            o.w = fmaf(c0, r.w, b4.w);
            o4[idx] = o;
        }
    }
}

// ---------------- one diffusion hop (fp16 state), fused output accumulate ---
// warp per node: r = dinv[i]*(sum_e dinv[src]*h[src]) + dinv[i]^2 * h[i]
// hout[i] = fp16(r) ; out[i] += coeff[k]*r   (out stays fp32)
__global__ void __launch_bounds__(256) k_hop(
    int flip, int k, int n, float4* __restrict__ out)
{
    int gw = (blockIdx.x * blockDim.x + threadIdx.x) >> 5;
    if (gw >= n) return;
    int lane = threadIdx.x & 31;

    const uint2* __restrict__ hin  = flip ? (const uint2*)g_bufB : (const uint2*)g_bufA;
    uint2*       __restrict__ hout = flip ? (uint2*)g_bufA       : (uint2*)g_bufB;

    int beg = g_rowptr[gw];
    int end = g_rowptr[gw + 1];

    float4 acc  = make_float4(0.f,0.f,0.f,0.f);
    float4 acc2 = make_float4(0.f,0.f,0.f,0.f);

    int e = beg;
    for (; e + 4 <= end; e += 4) {
        int   s0 = __ldg(&g_csr_src[e]);
        int   s1 = __ldg(&g_csr_src[e + 1]);
        int   s2 = __ldg(&g_csr_src[e + 2]);
        int   s3 = __ldg(&g_csr_src[e + 3]);
        float w0 = __ldg(&g_csr_w[e]);
        float w1 = __ldg(&g_csr_w[e + 1]);
        float w2 = __ldg(&g_csr_w[e + 2]);
        float w3 = __ldg(&g_csr_w[e + 3]);
        uint2 p0 = __ldg(&hin[s0 * DH2 + lane]);
        uint2 p1 = __ldg(&hin[s1 * DH2 + lane]);
        uint2 p2 = __ldg(&hin[s2 * DH2 + lane]);
        uint2 p3 = __ldg(&hin[s3 * DH2 + lane]);
        fma_h4(p0, w0, acc);
        fma_h4(p1, w1, acc2);
        fma_h4(p2, w2, acc);
        fma_h4(p3, w3, acc2);
    }
    for (; e < end; ++e) {
        int   s = __ldg(&g_csr_src[e]);
        float w = __ldg(&g_csr_w[e]);
        uint2 p = __ldg(&hin[s * DH2 + lane]);
        fma_h4(p, w, acc);
    }

    float di  = g_dinv[gw];
    float di2 = di * di;
    uint2 ps = __ldg(&hin[gw * DH2 + lane]);
    float2 slo = __half22float2(*(const __half2*)&ps.x);
    float2 shi = __half22float2(*(const __half2*)&ps.y);

    float4 r;
    r.x = fmaf(di, acc.x + acc2.x, di2 * slo.x);
    r.y = fmaf(di, acc.y + acc2.y, di2 * slo.y);
    r.z = fmaf(di, acc.z + acc2.z, di2 * shi.x);
    r.w = fmaf(di, acc.w + acc2.w, di2 * shi.y);

    int idx = gw * DH2 + lane;
    hout[idx] = pack_h4(r);

    float c = g_coeff[k];
    float4 o = out[idx];
    o.x = fmaf(c, r.x, o.x);
    o.y = fmaf(c, r.y, o.y);
    o.z = fmaf(c, r.z, o.z);
    o.w = fmaf(c, r.w, o.w);
    out[idx] = o;
}

// ---------------- launch ----------------------------------------------------
extern "C" void kernel_launch(void* const* d_in, const int* in_sizes, int n_in,
                              void* d_out, int out_size) {
    const float* x  = (const float*)d_in[0];
    const void*  ei = d_in[1];
    const float* t  = (const float*)d_in[2];
    const float* W  = (const float*)d_in[3];
    const float* b  = (const float*)d_in[4];
    float* out = (float*)d_out;

    int N = in_sizes[0] / D;
    int E = in_sizes[1] / 2;

    k_detect<<<1, 1>>>(ei);
    k_coeff<<<1, 1>>>(t);
    k_zero<<<(N + 255) / 256, 256>>>(N);
    k_hist<<<(E + 255) / 256, 256>>>(ei, E);
    k_scan<<<1, 1024>>>(N);
    k_prep<<<(N + 255) / 256, 256>>>(N);
    k_scatter<<<(E + 255) / 256, 256>>>(ei, E);
    k_transpose<<<(D * D + 255) / 256, 256>>>(W);
    k_gemm_init<<<(N + 31) / 32, 256>>>(x, b, out, N);

    int hop_blocks = (N + 7) / 8;   // 8 warps per block, warp per node
    for (int k = 1; k <= KHOPS; ++k) {
        int flip = (k - 1) & 1;
        k_hop<<<hop_blocks, 256>>>(flip, k, N, (float4*)out);
    }
}

// round 5
// speedup vs baseline: 1.0583x; 1.0583x over previous
#include <cuda_runtime.h>
#include <cuda_fp16.h>

#define D      128
#define D4     32          // D/4 float4 per row (fp32 views)
#define DH2    32          // D/4 uint2 per row (fp16 views: 4 halves per uint2)
#define KHOPS  10

static const int NMAX = 50000;
static const int EMAX = 625000;

// ---------------- scratch (device globals; no allocation allowed) ----------
__device__ __half g_bufA[NMAX * D];     // h ping (fp16 state)
__device__ __half g_bufB[NMAX * D];     // h pong
__device__ int    g_deg[NMAX];
__device__ int    g_rowptr[NMAX + 1];
__device__ int    g_cursor[NMAX];
__device__ float  g_dinv[NMAX];
__device__ int    g_csr_src[EMAX];
__device__ float  g_csr_w[EMAX];        // dinv[src] pre-gathered
__device__ float  g_Wt[D * D];          // W transposed: Wt[k][o]
__device__ float  g_coeff[KHOPS + 1];
__device__ int    g_is64;

// ---------------- small setup kernels ---------------------------------------

// Detect whether edge_index is int64 (odd 32-bit words all zero) or int32.
__global__ void k_detect(const void* __restrict__ ei) {
    const int* a = (const int*)ei;
    int is64 = 1;
#pragma unroll
    for (int i = 1; i < 32; i += 2)
        if (a[i] != 0) is64 = 0;
    g_is64 = is64;
}

__device__ __forceinline__ int load_idx(const void* ei, long long pos) {
    if (g_is64) return (int)((const long long*)ei)[pos];
    return ((const int*)ei)[pos];
}

// coeff[k] = e^{-t} * t^k / k!
__global__ void k_coeff(const float* __restrict__ t_ptr) {
    float t = *t_ptr;
    float c = expf(-t);
    g_coeff[0] = c;
    for (int k = 1; k <= KHOPS; ++k) { c = c * t / (float)k; g_coeff[k] = c; }
}

__global__ void k_zero(int n) {
    int i = blockIdx.x * blockDim.x + threadIdx.x;
    if (i < n) g_deg[i] = 0;
}

__global__ void k_hist(const void* __restrict__ ei, int E) {
    int e = blockIdx.x * blockDim.x + threadIdx.x;
    if (e < E) {
        int dst = load_idx(ei, (long long)E + e);
        atomicAdd(&g_deg[dst], 1);
    }
}

// Single-block exclusive scan: thread-sequential chunks + shfl warp/block scan.
__global__ void __launch_bounds__(1024) k_scan(int n) {
    const int T = 1024;
    int tid  = threadIdx.x;
    int per  = (n + T - 1) / T;
    int s    = tid * per;
    int epos = s + per; if (epos > n) epos = n; if (s > n) s = n;

    int sum = 0;
    for (int i = s; i < epos; ++i) sum += g_deg[i];

    int lane = tid & 31, wid = tid >> 5;
    int v = sum;
#pragma unroll
    for (int off = 1; off < 32; off <<= 1) {
        int t = __shfl_up_sync(0xffffffffu, v, off);
        if (lane >= off) v += t;
    }
    __shared__ int wsum[32];
    if (lane == 31) wsum[wid] = v;
    __syncthreads();
    if (wid == 0) {
        int wv = wsum[lane];
#pragma unroll
        for (int off = 1; off < 32; off <<= 1) {
            int t = __shfl_up_sync(0xffffffffu, wv, off);
            if (lane >= off) wv += t;
        }
        wsum[lane] = wv;
    }
    __syncthreads();

    int excl = v - sum + (wid ? wsum[wid - 1] : 0);
    int run = excl;
    for (int i = s; i < epos; ++i) { g_rowptr[i] = run; run += g_deg[i]; }
    if (tid == T - 1) g_rowptr[n] = run;   // last thread's run == grand total
}

// cursor = rowptr copy; dinv = rsqrt(indeg + 1)  (+1 = self loop)
__global__ void k_prep(int n) {
    int i = blockIdx.x * blockDim.x + threadIdx.x;
    if (i < n) {
        g_cursor[i] = g_rowptr[i];
        g_dinv[i]   = rsqrtf((float)g_deg[i] + 1.0f);
    }
}

__global__ void k_scatter(const void* __restrict__ ei, int E) {
    int e = blockIdx.x * blockDim.x + threadIdx.x;
    if (e < E) {
        int src = load_idx(ei, e);
        int dst = load_idx(ei, (long long)E + e);
        int pos = atomicAdd(&g_cursor[dst], 1);
        g_csr_src[pos] = src;
        g_csr_w[pos]   = g_dinv[src];
    }
}

__global__ void k_transpose(const float* __restrict__ W) {
    int i = blockIdx.x * blockDim.x + threadIdx.x;
    if (i < D * D) {
        int r = i / D, c = i % D;
        g_Wt[c * D + r] = W[r * D + c];
    }
}

// ------------- fp16 pack/unpack helpers -------------------------------------
__device__ __forceinline__ void fma_h4(uint2 p, float w, float4& a) {
    float2 lo = __half22float2(*(const __half2*)&p.x);
    float2 hi = __half22float2(*(const __half2*)&p.y);
    a.x = fmaf(w, lo.x, a.x); a.y = fmaf(w, lo.y, a.y);
    a.z = fmaf(w, hi.x, a.z); a.w = fmaf(w, hi.y, a.w);
}
__device__ __forceinline__ uint2 pack_h4(float4 r) {
    __half2 lo = __floats2half2_rn(r.x, r.y);
    __half2 hi = __floats2half2_rn(r.z, r.w);
    uint2 p;
    p.x = *(const unsigned int*)&lo;
    p.y = *(const unsigned int*)&hi;
    return p;
}

// ---------------- y = x @ W^T ; h0 = fp16(y) ; out = c0*y + b ---------------
// 256 threads = 8 warps; block computes 32 rows; x tile staged in smem.
// Inner loop vectorized: one float4 smem read per row covers 4 k-steps.
__global__ void __launch_bounds__(256) k_gemm_init(
    const float* __restrict__ x, const float* __restrict__ b,
    float* __restrict__ out, int n)
{
    __shared__ float sx[32 * D];
    int tid  = threadIdx.x;
    int warp = tid >> 5;
    int lane = tid & 31;
    int rowb = blockIdx.x * 32;
    int rows = n - rowb; if (rows > 32) rows = 32;

    const float4* x4 = (const float4*)(x + (long long)rowb * D);
    float4* sx4 = (float4*)sx;
    for (int i = tid; i < rows * D4; i += 256) sx4[i] = x4[i];
    __syncthreads();

    int r0 = warp * 4;
    if (rowb + r0 >= n) return;
    int nr = rows - r0; if (nr > 4) nr = 4; if (nr < 0) nr = 0;

    const float4* __restrict__ Wt4 = (const float4*)g_Wt;

    float4 a0 = make_float4(0.f,0.f,0.f,0.f), a1 = a0, a2 = a0, a3 = a0;

#pragma unroll 2
    for (int kc = 0; kc < D; kc += 4) {
        int kq = kc >> 2;
        float4 xv0 =             sx4[(r0 + 0) * D4 + kq];
        float4 xv1 = (nr > 1) ?  sx4[(r0 + 1) * D4 + kq] : make_float4(0,0,0,0);
        float4 xv2 = (nr > 2) ?  sx4[(r0 + 2) * D4 + kq] : make_float4(0,0,0,0);
        float4 xv3 = (nr > 3) ?  sx4[(r0 + 3) * D4 + kq] : make_float4(0,0,0,0);
#pragma unroll
        for (int j = 0; j < 4; ++j) {
            float4 w = __ldg(&Wt4[(kc + j) * D4 + lane]);
            float v0 = j==0?xv0.x : j==1?xv0.y : j==2?xv0.z : xv0.w;
            float v1 = j==0?xv1.x : j==1?xv1.y : j==2?xv1.z : xv1.w;
            float v2 = j==0?xv2.x : j==1?xv2.y : j==2?xv2.z : xv2.w;
            float v3 = j==0?xv3.x : j==1?xv3.y : j==2?xv3.z : xv3.w;
            a0.x = fmaf(v0, w.x, a0.x); a0.y = fmaf(v0, w.y, a0.y);
            a0.z = fmaf(v0, w.z, a0.z); a0.w = fmaf(v0, w.w, a0.w);
            a1.x = fmaf(v1, w.x, a1.x); a1.y = fmaf(v1, w.y, a1.y);
            a1.z = fmaf(v1, w.z, a1.z); a1.w = fmaf(v1, w.w, a1.w);
            a2.x = fmaf(v2, w.x, a2.x); a2.y = fmaf(v2, w.y, a2.y);
            a2.z = fmaf(v2, w.z, a2.z); a2.w = fmaf(v2, w.w, a2.w);
            a3.x = fmaf(v3, w.x, a3.x); a3.y = fmaf(v3, w.y, a3.y);
            a3.z = fmaf(v3, w.z, a3.z); a3.w = fmaf(v3, w.w, a3.w);
        }
    }

    float c0 = g_coeff[0];
    float4 b4 = __ldg(&((const float4*)b)[lane]);
    uint2*  h0 = (uint2*)g_bufA;
    float4* o4 = (float4*)out;

    float4 accs[4] = {a0, a1, a2, a3};
#pragma unroll
    for (int j = 0; j < 4; ++j) {
        if (j < nr) {
            int idx = (rowb + r0 + j) * D4 + lane;
            float4 r = accs[j];
            h0[idx] = pack_h4(r);
            float4 o;
            o.x = fmaf(c0, r.x, b4.x);
            o.y = fmaf(c0, r.y, b4.y);
            o.z = fmaf(c0, r.z, b4.z);
            o.w = fmaf(c0, r.w, b4.w);
            o4[idx] = o;
        }
    }
}

// ---------------- one diffusion hop (fp16 state) -----------------------------
// warp per node: r = dinv[i]*(sum_e dinv[src]*h[src]) + dinv[i]^2 * h[i]
// write_h: store hout[i] = fp16(r)          (skipped on the final hop)
// do_out : out[i] += coeff[k-1]*hin[i] + coeff[k]*r   (even hops only — pairs
//          two Taylor terms per out RMW, halving out traffic)
__global__ void __launch_bounds__(256) k_hop(
    int flip, int k, int n, float4* __restrict__ out, int do_out, int write_h)
{
    int gw = (blockIdx.x * blockDim.x + threadIdx.x) >> 5;
    if (gw >= n) return;
    int lane = threadIdx.x & 31;

    const uint2* __restrict__ hin  = flip ? (const uint2*)g_bufB : (const uint2*)g_bufA;
    uint2*       __restrict__ hout = flip ? (uint2*)g_bufA       : (uint2*)g_bufB;

    int beg = g_rowptr[gw];
    int end = g_rowptr[gw + 1];

    float4 acc  = make_float4(0.f,0.f,0.f,0.f);
    float4 acc2 = make_float4(0.f,0.f,0.f,0.f);

    int e = beg;
    // 8-deep unroll: 8 independent gathers in flight (MLP=8)
    for (; e + 8 <= end; e += 8) {
        int   s0 = __ldg(&g_csr_src[e + 0]);
        int   s1 = __ldg(&g_csr_src[e + 1]);
        int   s2 = __ldg(&g_csr_src[e + 2]);
        int   s3 = __ldg(&g_csr_src[e + 3]);
        int   s4 = __ldg(&g_csr_src[e + 4]);
        int   s5 = __ldg(&g_csr_src[e + 5]);
        int   s6 = __ldg(&g_csr_src[e + 6]);
        int   s7 = __ldg(&g_csr_src[e + 7]);
        uint2 p0 = __ldg(&hin[s0 * DH2 + lane]);
        uint2 p1 = __ldg(&hin[s1 * DH2 + lane]);
        uint2 p2 = __ldg(&hin[s2 * DH2 + lane]);
        uint2 p3 = __ldg(&hin[s3 * DH2 + lane]);
        uint2 p4 = __ldg(&hin[s4 * DH2 + lane]);
        uint2 p5 = __ldg(&hin[s5 * DH2 + lane]);
        uint2 p6 = __ldg(&hin[s6 * DH2 + lane]);
        uint2 p7 = __ldg(&hin[s7 * DH2 + lane]);
        float w0 = __ldg(&g_csr_w[e + 0]);
        float w1 = __ldg(&g_csr_w[e + 1]);
        float w2 = __ldg(&g_csr_w[e + 2]);
        float w3 = __ldg(&g_csr_w[e + 3]);
        float w4 = __ldg(&g_csr_w[e + 4]);
        float w5 = __ldg(&g_csr_w[e + 5]);
        float w6 = __ldg(&g_csr_w[e + 6]);
        float w7 = __ldg(&g_csr_w[e + 7]);
        fma_h4(p0, w0, acc);  fma_h4(p1, w1, acc2);
        fma_h4(p2, w2, acc);  fma_h4(p3, w3, acc2);
        fma_h4(p4, w4, acc);  fma_h4(p5, w5, acc2);
        fma_h4(p6, w6, acc);  fma_h4(p7, w7, acc2);
    }
    for (; e + 4 <= end; e += 4) {
        int   s0 = __ldg(&g_csr_src[e + 0]);
        int   s1 = __ldg(&g_csr_src[e + 1]);
        int   s2 = __ldg(&g_csr_src[e + 2]);
        int   s3 = __ldg(&g_csr_src[e + 3]);
        uint2 p0 = __ldg(&hin[s0 * DH2 + lane]);
        uint2 p1 = __ldg(&hin[s1 * DH2 + lane]);
        uint2 p2 = __ldg(&hin[s2 * DH2 + lane]);
        uint2 p3 = __ldg(&hin[s3 * DH2 + lane]);
        float w0 = __ldg(&g_csr_w[e + 0]);
        float w1 = __ldg(&g_csr_w[e + 1]);
        float w2 = __ldg(&g_csr_w[e + 2]);
        float w3 = __ldg(&g_csr_w[e + 3]);
        fma_h4(p0, w0, acc);  fma_h4(p1, w1, acc2);
        fma_h4(p2, w2, acc);  fma_h4(p3, w3, acc2);
    }
    for (; e < end; ++e) {
        int   s = __ldg(&g_csr_src[e]);
        float w = __ldg(&g_csr_w[e]);
        uint2 p = __ldg(&hin[s * DH2 + lane]);
        fma_h4(p, w, acc);
    }

    float di  = g_dinv[gw];
    float di2 = di * di;
    uint2 ps = __ldg(&hin[gw * DH2 + lane]);
    float2 slo = __half22float2(*(const __half2*)&ps.x);
    float2 shi = __half22float2(*(const __half2*)&ps.y);

    float4 r;
    r.x = fmaf(di, acc.x + acc2.x, di2 * slo.x);
    r.y = fmaf(di, acc.y + acc2.y, di2 * slo.y);
    r.z = fmaf(di, acc.z + acc2.z, di2 * shi.x);
    r.w = fmaf(di, acc.w + acc2.w, di2 * shi.y);

    int idx = gw * DH2 + lane;
    if (write_h) hout[idx] = pack_h4(r);

    if (do_out) {
        float cp = g_coeff[k - 1];   // term for h_{k-1} (== hin self value)
        float c  = g_coeff[k];       // term for h_k (== r)
        float4 o = out[idx];
        o.x = fmaf(cp, slo.x, o.x);
        o.y = fmaf(cp, slo.y, o.y);
        o.z = fmaf(cp, shi.x, o.z);
        o.w = fmaf(cp, shi.y, o.w);
        o.x = fmaf(c, r.x, o.x);
        o.y = fmaf(c, r.y, o.y);
        o.z = fmaf(c, r.z, o.z);
        o.w = fmaf(c, r.w, o.w);
        out[idx] = o;
    }
}

// ---------------- launch ----------------------------------------------------
extern "C" void kernel_launch(void* const* d_in, const int* in_sizes, int n_in,
                              void* d_out, int out_size) {
    const float* x  = (const float*)d_in[0];
    const void*  ei = d_in[1];
    const float* t  = (const float*)d_in[2];
    const float* W  = (const float*)d_in[3];
    const float* b  = (const float*)d_in[4];
    float* out = (float*)d_out;

    int N = in_sizes[0] / D;
    int E = in_sizes[1] / 2;

    k_detect<<<1, 1>>>(ei);
    k_coeff<<<1, 1>>>(t);
    k_zero<<<(N + 255) / 256, 256>>>(N);
    k_hist<<<(E + 255) / 256, 256>>>(ei, E);
    k_scan<<<1, 1024>>>(N);
    k_prep<<<(N + 255) / 256, 256>>>(N);
    k_scatter<<<(E + 255) / 256, 256>>>(ei, E);
    k_transpose<<<(D * D + 255) / 256, 256>>>(W);
    k_gemm_init<<<(N + 31) / 32, 256>>>(x, b, out, N);

    int hop_blocks = (N + 7) / 8;   // 8 warps per block, warp per node
    for (int k = 1; k <= KHOPS; ++k) {
        int flip   = (k - 1) & 1;
        int do_out = (k & 1) == 0;          // even hops add two Taylor terms
        int write_h = (k < KHOPS);          // final h never read again
        k_hop<<<hop_blocks, 256>>>(flip, k, N, (float4*)out, do_out, write_h);
    }
}